// round 2
// baseline (speedup 1.0000x reference)
#include <cuda_runtime.h>
#include <cstdint>

#define NN 50000
#define NE 400000

// ---------------- scratch (static device globals; no allocation at runtime) ----
__device__ float g_A[(size_t)NN * 512];    // GEMM outputs / L1 pre-agg
__device__ float g_B[(size_t)NN * 1024];   // activations
__device__ float g_C[(size_t)NN * 512];    // scatter accumulators
__device__ float g_dinv[NN];
__device__ float g_norm[NE];

// ---------------- helpers ------------------------------------------------------
__device__ __forceinline__ void red_add_v4(float* addr, float4 v) {
    asm volatile("red.global.add.v4.f32 [%0], {%1, %2, %3, %4};"
                 :: "l"(addr), "f"(v.x), "f"(v.y), "f"(v.z), "f"(v.w)
                 : "memory");
}

__global__ void k_fill1(float* p, int n) {
    int i = blockIdx.x * blockDim.x + threadIdx.x;
    if (i < n) p[i] = 1.0f;
}

__global__ void k_count(const int* __restrict__ dst, float* deg) {
    int e = blockIdx.x * blockDim.x + threadIdx.x;
    if (e < NE) atomicAdd(&deg[dst[e]], 1.0f);
}

__global__ void k_rsqrt_ip(float* p, int n) {
    int i = blockIdx.x * blockDim.x + threadIdx.x;
    if (i < n) p[i] = rsqrtf(p[i]);
}

__global__ void k_norm(const int* __restrict__ src, const int* __restrict__ dst,
                       const float* __restrict__ dinv, float* __restrict__ norm) {
    int e = blockIdx.x * blockDim.x + threadIdx.x;
    if (e < NE) norm[e] = dinv[src[e]] * dinv[dst[e]];
}

// agg[i,:] = dinv[i]^2 * h[i,:]   (self-loop contribution; also initializes agg)
template<int F4>
__global__ void k_selfinit(const float* __restrict__ h, const float* __restrict__ dinv,
                           float* __restrict__ agg) {
    long long idx = (long long)blockIdx.x * blockDim.x + threadIdx.x;
    if (idx >= (long long)NN * F4) return;
    int i = (int)(idx / F4);
    float s = dinv[i]; s *= s;
    float4 v = ((const float4*)h)[idx];
    v.x *= s; v.y *= s; v.z *= s; v.w *= s;
    ((float4*)agg)[idx] = v;
}

// agg[dst[e],:] += norm[e] * h[src[e],:]   via 16B vector reductions
template<int F4>
__global__ void k_scatter(const float* __restrict__ h, float* __restrict__ agg,
                          const int* __restrict__ src, const int* __restrict__ dst,
                          const float* __restrict__ norm) {
    long long idx = (long long)blockIdx.x * blockDim.x + threadIdx.x;
    if (idx >= (long long)NE * F4) return;
    int e = (int)(idx / F4);
    int f = (int)(idx - (long long)e * F4);
    int s = src[e], d = dst[e];
    float w = norm[e];
    float4 v = ((const float4*)h)[(long long)s * F4 + f];
    v.x *= w; v.y *= w; v.z *= w; v.w *= w;
    red_add_v4((float*)(((float4*)agg) + (long long)d * F4 + f), v);
}

template<int F4>
__global__ void k_bias_relu(const float* __restrict__ in, const float* __restrict__ b,
                            float* __restrict__ out) {
    long long idx = (long long)blockIdx.x * blockDim.x + threadIdx.x;
    if (idx >= (long long)NN * F4) return;
    int f = (int)(idx % F4);
    float4 bb = ((const float4*)b)[f];
    float4 v = ((const float4*)in)[idx];
    v.x = fmaxf(v.x + bb.x, 0.f);
    v.y = fmaxf(v.y + bb.y, 0.f);
    v.z = fmaxf(v.z + bb.z, 0.f);
    v.w = fmaxf(v.w + bb.w, 0.f);
    ((float4*)out)[idx] = v;
}

// ---------------- SGEMM: out[M,F] = A[M,K] @ W[K,F] (+bias, relu) --------------
template<int BM, int BN, int BK, int TM, int TN, bool EPI>
__global__ void __launch_bounds__((BM / TM) * (BN / TN))
sgemm_kernel(const float* __restrict__ A, const float* __restrict__ W,
             const float* __restrict__ bias, float* __restrict__ out,
             int M, int K, int F) {
    constexpr int THREADS = (BM / TM) * (BN / TN);
    __shared__ float As[BK][BM + 4];
    __shared__ float Ws[BK][BN];
    const int tid  = threadIdx.x;
    const int tcol = tid % (BN / TN);
    const int trow = tid / (BN / TN);
    const int m0 = blockIdx.y * BM;
    const int n0 = blockIdx.x * BN;

    float acc[TM][TN];
#pragma unroll
    for (int i = 0; i < TM; i++)
#pragma unroll
        for (int j = 0; j < TN; j++) acc[i][j] = 0.f;

    constexpr int KV = BK / 4;                 // float4 per A row slab
    constexpr int A_ROWS_ITER = THREADS / KV;
    constexpr int A_LOADS = BM / A_ROWS_ITER;
    const int a_r = tid / KV;
    const int a_c = (tid % KV) * 4;
    constexpr int NV = BN / 4;
    constexpr int W_ROWS_ITER = THREADS / NV;
    constexpr int W_LOADS = BK / W_ROWS_ITER;
    const int w_r = tid / NV;
    const int w_c = (tid % NV) * 4;

    for (int k0 = 0; k0 < K; k0 += BK) {
#pragma unroll
        for (int i = 0; i < A_LOADS; i++) {
            int r  = a_r + i * A_ROWS_ITER;
            int gm = m0 + r;
            float4 v = make_float4(0.f, 0.f, 0.f, 0.f);
            if (gm < M) v = *(const float4*)(A + (long long)gm * K + k0 + a_c);
            As[a_c + 0][r] = v.x; As[a_c + 1][r] = v.y;
            As[a_c + 2][r] = v.z; As[a_c + 3][r] = v.w;
        }
#pragma unroll
        for (int i = 0; i < W_LOADS; i++) {
            int kr = w_r + i * W_ROWS_ITER;
            float4 v = *(const float4*)(W + (long long)(k0 + kr) * F + n0 + w_c);
            *(float4*)&Ws[kr][w_c] = v;
        }
        __syncthreads();
#pragma unroll
        for (int k = 0; k < BK; k++) {
            float ra[TM], rb[TN];
#pragma unroll
            for (int i = 0; i < TM; i++) ra[i] = As[k][trow * TM + i];
#pragma unroll
            for (int j = 0; j < TN; j++) rb[j] = Ws[k][tcol * TN + j];
#pragma unroll
            for (int i = 0; i < TM; i++)
#pragma unroll
                for (int j = 0; j < TN; j++)
                    acc[i][j] = fmaf(ra[i], rb[j], acc[i][j]);
        }
        __syncthreads();
    }

#pragma unroll
    for (int i = 0; i < TM; i++) {
        int gm = m0 + trow * TM + i;
        if (gm >= M) continue;
#pragma unroll
        for (int j = 0; j < TN; j += 4) {
            int gn = n0 + tcol * TN + j;
            float4 v = make_float4(acc[i][j], acc[i][j + 1], acc[i][j + 2], acc[i][j + 3]);
            if constexpr (EPI) {
                const float4 bb = *(const float4*)(bias + gn);
                v.x = fmaxf(v.x + bb.x, 0.f);
                v.y = fmaxf(v.y + bb.y, 0.f);
                v.z = fmaxf(v.z + bb.z, 0.f);
                v.w = fmaxf(v.w + bb.w, 0.f);
            }
            *(float4*)(out + (long long)gm * F + gn) = v;
        }
    }
}

// ---------------- last layer (K=64 -> F=1): warp-per-row GEMV ------------------
__global__ void k_gemv64(const float* __restrict__ X, const float* __restrict__ w,
                         float* __restrict__ out) {
    int gt   = blockIdx.x * blockDim.x + threadIdx.x;
    int row  = gt >> 5;
    int lane = gt & 31;
    if (row >= NN) return;
    float s = X[(long long)row * 64 + lane] * w[lane]
            + X[(long long)row * 64 + 32 + lane] * w[32 + lane];
#pragma unroll
    for (int o = 16; o; o >>= 1) s += __shfl_down_sync(0xffffffffu, s, o);
    if (lane == 0) out[row] = s;
}

__global__ void k_selfinit1(const float* __restrict__ h, const float* __restrict__ dinv,
                            float* __restrict__ agg) {
    int i = blockIdx.x * blockDim.x + threadIdx.x;
    if (i >= NN) return;
    float s = dinv[i];
    agg[i] = s * s * h[i];
}

__global__ void k_scatter1(const float* __restrict__ h, float* __restrict__ agg,
                           const int* __restrict__ src, const int* __restrict__ dst,
                           const float* __restrict__ norm) {
    int e = blockIdx.x * blockDim.x + threadIdx.x;
    if (e >= NE) return;
    atomicAdd(&agg[dst[e]], norm[e] * h[src[e]]);
}

__global__ void k_final(const float* __restrict__ in, const float* __restrict__ b,
                        float* __restrict__ out) {
    int i = blockIdx.x * blockDim.x + threadIdx.x;
    if (i >= NN) return;
    out[i] = fmaxf(in[i] + b[0], 0.f);
}

// ---------------- driver -------------------------------------------------------
static inline int cdiv(long long a, long long b) { return (int)((a + b - 1) / b); }

extern "C" void kernel_launch(void* const* d_in, const int* in_sizes, int n_in,
                              void* d_out, int out_size) {
    const float* x   = (const float*)d_in[0];
    const int*   src = (const int*)d_in[1];
    const int*   dst = src + NE;
    const float* W1 = (const float*)d_in[2];  const float* b1 = (const float*)d_in[3];
    const float* W2 = (const float*)d_in[4];  const float* b2 = (const float*)d_in[5];
    const float* W3 = (const float*)d_in[6];  const float* b3 = (const float*)d_in[7];
    const float* W4 = (const float*)d_in[8];  const float* b4 = (const float*)d_in[9];
    const float* W5 = (const float*)d_in[10]; const float* b5 = (const float*)d_in[11];
    float* out = (float*)d_out;

    float *A, *B, *C, *dinv, *norm;
    cudaGetSymbolAddress((void**)&A, g_A);
    cudaGetSymbolAddress((void**)&B, g_B);
    cudaGetSymbolAddress((void**)&C, g_C);
    cudaGetSymbolAddress((void**)&dinv, g_dinv);
    cudaGetSymbolAddress((void**)&norm, g_norm);

    const int T = 256;

    // --- degree / normalization (deg includes self-loop: start at 1) ---
    k_fill1<<<cdiv(NN, T), T>>>(dinv, NN);
    k_count<<<cdiv(NE, T), T>>>(dst, dinv);
    k_rsqrt_ip<<<cdiv(NN, T), T>>>(dinv, NN);
    k_norm<<<cdiv(NE, T), T>>>(src, dst, dinv, norm);

    // --- Layer 1: 128 -> 1024. Pre-aggregate x (width 128), then GEMM+bias+relu.
    k_selfinit<32><<<cdiv((long long)NN * 32, T), T>>>(x, dinv, A);
    k_scatter<32><<<cdiv((long long)NE * 32, T), T>>>(x, A, src, dst, norm);
    {
        dim3 g(1024 / 128, cdiv(NN, 128));
        sgemm_kernel<128, 128, 16, 8, 8, true><<<g, 256>>>(A, W1, b1, B, NN, 128, 1024);
    }

    // --- Layer 2: 1024 -> 512. GEMM, then scatter (width 512), bias+relu.
    {
        dim3 g(512 / 128, cdiv(NN, 128));
        sgemm_kernel<128, 128, 16, 8, 8, false><<<g, 256>>>(B, W2, nullptr, A, NN, 1024, 512);
    }
    k_selfinit<128><<<cdiv((long long)NN * 128, T), T>>>(A, dinv, C);
    k_scatter<128><<<cdiv((long long)NE * 128, T), T>>>(A, C, src, dst, norm);
    k_bias_relu<128><<<cdiv((long long)NN * 128, T), T>>>(C, b2, B);

    // --- Layer 3: 512 -> 256.
    {
        dim3 g(256 / 128, cdiv(NN, 128));
        sgemm_kernel<128, 128, 16, 8, 8, false><<<g, 256>>>(B, W3, nullptr, A, NN, 512, 256);
    }
    k_selfinit<64><<<cdiv((long long)NN * 64, T), T>>>(A, dinv, C);
    k_scatter<64><<<cdiv((long long)NE * 64, T), T>>>(A, C, src, dst, norm);
    k_bias_relu<64><<<cdiv((long long)NN * 64, T), T>>>(C, b3, B);

    // --- Layer 4: 256 -> 64.
    {
        dim3 g(1, cdiv(NN, 128));
        sgemm_kernel<128, 64, 16, 8, 4, false><<<g, 256>>>(B, W4, nullptr, A, NN, 256, 64);
    }
    k_selfinit<16><<<cdiv((long long)NN * 16, T), T>>>(A, dinv, C);
    k_scatter<16><<<cdiv((long long)NE * 16, T), T>>>(A, C, src, dst, norm);
    k_bias_relu<16><<<cdiv((long long)NN * 16, T), T>>>(C, b4, B);

    // --- Layer 5: 64 -> 1. GEMV, scatter width 1, bias+relu into d_out.
    k_gemv64<<<cdiv((long long)NN * 32, T), T>>>(B, W5, A);
    k_selfinit1<<<cdiv(NN, T), T>>>(A, dinv, C);
    k_scatter1<<<cdiv(NE, T), T>>>(A, C, src, dst, norm);
    k_final<<<cdiv(NN, T), T>>>(C, b5, out);
}

// round 7
// speedup vs baseline: 2.0567x; 2.0567x over previous
#include <cuda_runtime.h>
#include <cuda_fp16.h>
#include <cstdint>

#define NN 50000
#define NE 400000

// ---------------- scratch (static device globals) ------------------------------
__device__ float g_A[(size_t)NN * 512];          // GEMM h outputs / L1 pre-agg
__device__ float g_C[(size_t)NN * 512];          // scatter accumulators
__device__ float g_B64[(size_t)NN * 64];         // layer-4 activations (fp32)
__device__ __half g_XA[(size_t)NN * 1024];       // split activations (hi|lo)
__device__ __half g_XB[(size_t)NN * 2048];       // split activations (hi|lo)
__device__ __half g_W3T[2408448];                // split transposed weights (3K wide)
__device__ float g_dinv[NN];
__device__ float g_norm[NE];

// W3T row-widths 3K; offsets in elements
#define W3T_OFF1 0
#define W3T_OFF2 393216
#define W3T_OFF3 1966080
#define W3T_OFF4 2359296

// ---------------- PTX helpers ---------------------------------------------------
__device__ __forceinline__ uint32_t smem_u32(const void* p) {
    uint32_t a;
    asm("{ .reg .u64 t; cvta.to.shared.u64 t, %1; cvt.u32.u64 %0, t; }" : "=r"(a) : "l"(p));
    return a;
}
__device__ __forceinline__ void cp16(uint32_t dst, const void* src) {
    asm volatile("cp.async.cg.shared.global [%0], [%1], 16;" :: "r"(dst), "l"(src));
}
__device__ __forceinline__ void cp_commit() { asm volatile("cp.async.commit_group;"); }
__device__ __forceinline__ void cp_wait1() { asm volatile("cp.async.wait_group 1;"); }
__device__ __forceinline__ void cp_wait0() { asm volatile("cp.async.wait_group 0;"); }

__device__ __forceinline__ void ldsm_x4(uint32_t& r0, uint32_t& r1, uint32_t& r2,
                                        uint32_t& r3, uint32_t addr) {
    asm volatile("ldmatrix.sync.aligned.m8n8.x4.shared.b16 {%0,%1,%2,%3}, [%4];"
                 : "=r"(r0), "=r"(r1), "=r"(r2), "=r"(r3) : "r"(addr));
}
__device__ __forceinline__ void mma16816(float* c, const uint32_t* a, const uint32_t* b) {
    asm volatile("mma.sync.aligned.m16n8k16.row.col.f32.f16.f16.f32 "
                 "{%0,%1,%2,%3}, {%4,%5,%6,%7}, {%8,%9}, {%0,%1,%2,%3};"
                 : "+f"(c[0]), "+f"(c[1]), "+f"(c[2]), "+f"(c[3])
                 : "r"(a[0]), "r"(a[1]), "r"(a[2]), "r"(a[3]), "r"(b[0]), "r"(b[1]));
}

__device__ __forceinline__ void split_h(float v, __half& hi, __half& lo) {
    hi = __float2half_rn(v);
    lo = __float2half_rn(v - __half2float(hi));
}
__device__ __forceinline__ uint32_t pack2(__half a, __half b) {
    __half2 p = __halves2half2(a, b);
    return *reinterpret_cast<uint32_t*>(&p);
}

// ---------------- misc kernels (degree / norm / scatter) ------------------------
__device__ __forceinline__ void red_add_v4(float* addr, float4 v) {
    asm volatile("red.global.add.v4.f32 [%0], {%1, %2, %3, %4};"
                 :: "l"(addr), "f"(v.x), "f"(v.y), "f"(v.z), "f"(v.w) : "memory");
}

__global__ void k_fill1(float* p, int n) {
    int i = blockIdx.x * blockDim.x + threadIdx.x;
    if (i < n) p[i] = 1.0f;
}
__global__ void k_count(const int* __restrict__ dst, float* deg) {
    int e = blockIdx.x * blockDim.x + threadIdx.x;
    if (e < NE) atomicAdd(&deg[dst[e]], 1.0f);
}
__global__ void k_rsqrt_ip(float* p, int n) {
    int i = blockIdx.x * blockDim.x + threadIdx.x;
    if (i < n) p[i] = rsqrtf(p[i]);
}
__global__ void k_norm(const int* __restrict__ src, const int* __restrict__ dst,
                       const float* __restrict__ dinv, float* __restrict__ norm) {
    int e = blockIdx.x * blockDim.x + threadIdx.x;
    if (e < NE) norm[e] = dinv[src[e]] * dinv[dst[e]];
}

template<int F4>
__global__ void k_selfinit(const float* __restrict__ h, const float* __restrict__ dinv,
                           float* __restrict__ agg) {
    long long idx = (long long)blockIdx.x * blockDim.x + threadIdx.x;
    if (idx >= (long long)NN * F4) return;
    int i = (int)(idx / F4);
    float s = dinv[i]; s *= s;
    float4 v = ((const float4*)h)[idx];
    v.x *= s; v.y *= s; v.z *= s; v.w *= s;
    ((float4*)agg)[idx] = v;
}

template<int F4>
__global__ void k_scatter(const float* __restrict__ h, float* __restrict__ agg,
                          const int* __restrict__ src, const int* __restrict__ dst,
                          const float* __restrict__ norm) {
    long long idx = (long long)blockIdx.x * blockDim.x + threadIdx.x;
    if (idx >= (long long)NE * F4) return;
    int e = (int)(idx / F4);
    int f = (int)(idx - (long long)e * F4);
    int s = src[e], d = dst[e];
    float w = norm[e];
    float4 v = ((const float4*)h)[(long long)s * F4 + f];
    v.x *= w; v.y *= w; v.z *= w; v.w *= w;
    red_add_v4((float*)(((float4*)agg) + (long long)d * F4 + f), v);
}

template<int F4>
__global__ void k_bias_relu(const float* __restrict__ in, const float* __restrict__ b,
                            float* __restrict__ out) {
    long long idx = (long long)blockIdx.x * blockDim.x + threadIdx.x;
    if (idx >= (long long)NN * F4) return;
    int f = (int)(idx % F4);
    float4 bb = ((const float4*)b)[f];
    float4 v = ((const float4*)in)[idx];
    v.x = fmaxf(v.x + bb.x, 0.f);
    v.y = fmaxf(v.y + bb.y, 0.f);
    v.z = fmaxf(v.z + bb.z, 0.f);
    v.w = fmaxf(v.w + bb.w, 0.f);
    ((float4*)out)[idx] = v;
}

// ---------------- split conversions ---------------------------------------------
// X layout per row (width 2K): [hi(0..K-1) | lo(0..K-1)]
template<int K>
__global__ void k_split_act(const float* __restrict__ in, __half* __restrict__ out) {
    long long idx = (long long)blockIdx.x * blockDim.x + threadIdx.x;
    if (idx >= (long long)NN * (K / 4)) return;
    int m = (int)(idx / (K / 4));
    int q = (int)(idx % (K / 4));
    int k = q * 4;
    float4 v = ((const float4*)in)[idx];
    __half h[4], l[4];
    split_h(v.x, h[0], l[0]); split_h(v.y, h[1], l[1]);
    split_h(v.z, h[2], l[2]); split_h(v.w, h[3], l[3]);
    __half* row = out + (size_t)m * (2 * K);
    *(uint2*)(row + k)     = make_uint2(pack2(h[0], h[1]), pack2(h[2], h[3]));
    *(uint2*)(row + K + k) = make_uint2(pack2(l[0], l[1]), pack2(l[2], l[3]));
}

template<int K>
__global__ void k_bias_relu_split(const float* __restrict__ in, const float* __restrict__ b,
                                  __half* __restrict__ out) {
    long long idx = (long long)blockIdx.x * blockDim.x + threadIdx.x;
    if (idx >= (long long)NN * (K / 4)) return;
    int m = (int)(idx / (K / 4));
    int q = (int)(idx % (K / 4));
    int k = q * 4;
    float4 v = ((const float4*)in)[idx];
    float4 bb = ((const float4*)b)[q];
    v.x = fmaxf(v.x + bb.x, 0.f);
    v.y = fmaxf(v.y + bb.y, 0.f);
    v.z = fmaxf(v.z + bb.z, 0.f);
    v.w = fmaxf(v.w + bb.w, 0.f);
    __half h[4], l[4];
    split_h(v.x, h[0], l[0]); split_h(v.y, h[1], l[1]);
    split_h(v.z, h[2], l[2]); split_h(v.w, h[3], l[3]);
    __half* row = out + (size_t)m * (2 * K);
    *(uint2*)(row + k)     = make_uint2(pack2(h[0], h[1]), pack2(h[2], h[3]));
    *(uint2*)(row + K + k) = make_uint2(pack2(l[0], l[1]), pack2(l[2], l[3]));
}

// W3T row n (width 3K): [Whi | Wlo | Whi], from W[k][n]
__global__ void k_split_w(const float* __restrict__ W, __half* __restrict__ out,
                          int K, int N) {
    long long idx = (long long)blockIdx.x * blockDim.x + threadIdx.x;
    if (idx >= (long long)K * N) return;
    int n = (int)(idx / K);
    int k = (int)(idx % K);
    float v = W[(size_t)k * N + n];
    __half h, l;
    split_h(v, h, l);
    __half* row = out + (size_t)n * (3 * K);
    row[k] = h;
    row[K + k] = l;
    row[2 * K + k] = h;
}

// ---------------- warp-MMA fp16 GEMM ---------------------------------------------
// C[M,N] = Asplit[M,2K] (logical [hi|hi|lo], 3K) @ W3T[N,3K]^T, fp32 accumulate.
// EPI 0: out = relu(C + bias) -> split fp16 to Xout (row width 2N)
// EPI 1: Hout = C ; Cout = dinv^2 * C
// Block: 256 thr (8 warps, 4x2), tile 128 x BN, BK=64, cp.async double-buffered.
template<int BN, int EPI>
__global__ void __launch_bounds__(256, 2)
gemm_mma(const __half* __restrict__ A2, const __half* __restrict__ W3T,
         int M, int K, int N,
         const float* __restrict__ bias,
         float* __restrict__ Hout, float* __restrict__ Cout,
         const float* __restrict__ dinv,
         __half* __restrict__ Xout) {
    extern __shared__ char smem[];
    constexpr int WN = BN / 2;      // warp N-tile
    constexpr int NT = WN / 8;      // n8 tiles per warp
    constexpr int A_SZ = 128 * 128; // bytes per stage
    constexpr int B_SZ = BN * 128;

    const int tid = threadIdx.x;
    const int m0 = blockIdx.y * 128;
    const int n0 = blockIdx.x * BN;
    const int Kphys = 2 * K;
    const int K3 = 3 * K;
    const int NCH = K3 >> 6;

    const uint32_t sA = smem_u32(smem);
    const uint32_t sB = sA + A_SZ;
    const uint32_t stageStride = A_SZ + B_SZ;

    const int lr = tid >> 3;        // loader row helper
    const int lc = tid & 7;         // loader chunk (16B)

    auto issue = [&](int ci) {
        const int s = ci & 1;
        const int kpos = ci * 64;
        const int aoff = (kpos >= K) ? kpos - K : kpos;
        const uint32_t dA = sA + s * stageStride;
        const uint32_t dB = sB + s * stageStride;
#pragma unroll
        for (int t = 0; t < 4; t++) {
            int r = lr + t * 32;
            int gm = m0 + r; if (gm >= M) gm = M - 1;
            const void* src = (const char*)A2 + ((size_t)gm * Kphys + aoff + lc * 8) * 2;
            cp16(dA + r * 128 + ((lc ^ (r & 7)) << 4), src);
        }
#pragma unroll
        for (int t = 0; t < BN / 32; t++) {
            int r = lr + t * 32;
            const void* src = (const char*)W3T + ((size_t)(n0 + r) * K3 + kpos + lc * 8) * 2;
            cp16(dB + r * 128 + ((lc ^ (r & 7)) << 4), src);
        }
        cp_commit();
    };

    const int w = tid >> 5, lane = tid & 31;
    const int wm = w & 3, wn = w >> 2;

    float acc[2][NT][4];
#pragma unroll
    for (int mt = 0; mt < 2; mt++)
#pragma unroll
        for (int nt = 0; nt < NT; nt++)
#pragma unroll
            for (int j = 0; j < 4; j++) acc[mt][nt][j] = 0.f;

    issue(0);
    for (int ci = 0; ci < NCH; ci++) {
        if (ci + 1 < NCH) { issue(ci + 1); cp_wait1(); }
        else              { cp_wait0(); }
        __syncthreads();
        const int s = ci & 1;
        const uint32_t stA = sA + s * stageStride;
        const uint32_t stB = sB + s * stageStride;
#pragma unroll
        for (int kk = 0; kk < 4; kk++) {
            uint32_t af[2][4];
#pragma unroll
            for (int mt = 0; mt < 2; mt++) {
                int row = wm * 32 + mt * 16 + (lane & 15);
                int c = kk * 2 + (lane >> 4);
                ldsm_x4(af[mt][0], af[mt][1], af[mt][2], af[mt][3],
                        stA + row * 128 + ((c ^ (row & 7)) << 4));
            }
            uint32_t bf[NT][2];
#pragma unroll
            for (int bt = 0; bt < NT / 2; bt++) {
                int j = lane >> 3;
                int row = wn * WN + bt * 16 + ((j >> 1) << 3) + (lane & 7);
                int c = kk * 2 + (j & 1);
                ldsm_x4(bf[2 * bt][0], bf[2 * bt][1], bf[2 * bt + 1][0], bf[2 * bt + 1][1],
                        stB + row * 128 + ((c ^ (row & 7)) << 4));
            }
#pragma unroll
            for (int mt = 0; mt < 2; mt++)
#pragma unroll
                for (int nt = 0; nt < NT; nt++)
                    mma16816(acc[mt][nt], af[mt], bf[nt]);
        }
        __syncthreads();
    }

    // ---------------- epilogue ----------------
#pragma unroll
    for (int mt = 0; mt < 2; mt++) {
#pragma unroll
        for (int rh = 0; rh < 2; rh++) {
            int row = wm * 32 + mt * 16 + rh * 8 + (lane >> 2);
            int gm = m0 + row;
            if (gm >= M) continue;
            if constexpr (EPI == 1) {
                float s = dinv[gm]; s *= s;
#pragma unroll
                for (int nt = 0; nt < NT; nt++) {
                    int col = n0 + wn * WN + nt * 8 + (lane & 3) * 2;
                    float c0 = acc[mt][nt][rh * 2], c1 = acc[mt][nt][rh * 2 + 1];
                    *(float2*)(Hout + (size_t)gm * N + col) = make_float2(c0, c1);
                    *(float2*)(Cout + (size_t)gm * N + col) = make_float2(s * c0, s * c1);
                }
            } else {
#pragma unroll
                for (int nt = 0; nt < NT; nt++) {
                    int col = n0 + wn * WN + nt * 8 + (lane & 3) * 2;
                    float v0 = fmaxf(acc[mt][nt][rh * 2]     + __ldg(bias + col),     0.f);
                    float v1 = fmaxf(acc[mt][nt][rh * 2 + 1] + __ldg(bias + col + 1), 0.f);
                    __half h0, l0, h1, l1;
                    split_h(v0, h0, l0);
                    split_h(v1, h1, l1);
                    size_t base = (size_t)gm * (size_t)(2 * N) + col;
                    *(uint32_t*)(Xout + base)     = pack2(h0, h1);
                    *(uint32_t*)(Xout + base + N) = pack2(l0, l1);
                }
            }
        }
    }
}

// ---------------- last layer (K=64 -> F=1) ----------------------------------------
__global__ void k_gemv64(const float* __restrict__ X, const float* __restrict__ w,
                         float* __restrict__ out) {
    int gt = blockIdx.x * blockDim.x + threadIdx.x;
    int row = gt >> 5;
    int lane = gt & 31;
    if (row >= NN) return;
    float s = X[(long long)row * 64 + lane] * w[lane]
            + X[(long long)row * 64 + 32 + lane] * w[32 + lane];
#pragma unroll
    for (int o = 16; o; o >>= 1) s += __shfl_down_sync(0xffffffffu, s, o);
    if (lane == 0) out[row] = s;
}

__global__ void k_selfinit1(const float* __restrict__ h, const float* __restrict__ dinv,
                            float* __restrict__ agg) {
    int i = blockIdx.x * blockDim.x + threadIdx.x;
    if (i >= NN) return;
    float s = dinv[i];
    agg[i] = s * s * h[i];
}
__global__ void k_scatter1(const float* __restrict__ h, float* __restrict__ agg,
                           const int* __restrict__ src, const int* __restrict__ dst,
                           const float* __restrict__ norm) {
    int e = blockIdx.x * blockDim.x + threadIdx.x;
    if (e >= NE) return;
    atomicAdd(&agg[dst[e]], norm[e] * h[src[e]]);
}
__global__ void k_final(const float* __restrict__ in, const float* __restrict__ b,
                        float* __restrict__ out) {
    int i = blockIdx.x * blockDim.x + threadIdx.x;
    if (i >= NN) return;
    out[i] = fmaxf(in[i] + b[0], 0.f);
}

// ---------------- driver ----------------------------------------------------------
static inline int cdiv(long long a, long long b) { return (int)((a + b - 1) / b); }

extern "C" void kernel_launch(void* const* d_in, const int* in_sizes, int n_in,
                              void* d_out, int out_size) {
    const float* x   = (const float*)d_in[0];
    const int*   src = (const int*)d_in[1];
    const int*   dst = src + NE;
    const float* W1 = (const float*)d_in[2];  const float* b1 = (const float*)d_in[3];
    const float* W2 = (const float*)d_in[4];  const float* b2 = (const float*)d_in[5];
    const float* W3 = (const float*)d_in[6];  const float* b3 = (const float*)d_in[7];
    const float* W4 = (const float*)d_in[8];  const float* b4 = (const float*)d_in[9];
    const float* W5 = (const float*)d_in[10]; const float* b5 = (const float*)d_in[11];
    float* out = (float*)d_out;

    float *A, *C, *B64, *dinv, *norm;
    __half *XA, *XB, *W3T;
    cudaGetSymbolAddress((void**)&A, g_A);
    cudaGetSymbolAddress((void**)&C, g_C);
    cudaGetSymbolAddress((void**)&B64, g_B64);
    cudaGetSymbolAddress((void**)&XA, g_XA);
    cudaGetSymbolAddress((void**)&XB, g_XB);
    cudaGetSymbolAddress((void**)&W3T, g_W3T);
    cudaGetSymbolAddress((void**)&dinv, g_dinv);
    cudaGetSymbolAddress((void**)&norm, g_norm);

    const int SMEM128 = 2 * (128 * 128 + 128 * 128);  // 65536
    const int SMEM64  = 2 * (128 * 128 + 64 * 128);   // 49152
    cudaFuncSetAttribute(gemm_mma<128, 0>, cudaFuncAttributeMaxDynamicSharedMemorySize, SMEM128);
    cudaFuncSetAttribute(gemm_mma<128, 1>, cudaFuncAttributeMaxDynamicSharedMemorySize, SMEM128);
    cudaFuncSetAttribute(gemm_mma<64, 1>,  cudaFuncAttributeMaxDynamicSharedMemorySize, SMEM64);

    const int T = 256;
    const int MB = cdiv(NN, 128);  // 391

    // degree / norm (deg includes self-loop: start at 1)
    k_fill1<<<cdiv(NN, T), T>>>(dinv, NN);
    k_count<<<cdiv(NE, T), T>>>(dst, dinv);
    k_rsqrt_ip<<<cdiv(NN, T), T>>>(dinv, NN);
    k_norm<<<cdiv(NE, T), T>>>(src, dst, dinv, norm);

    // weight splits
    k_split_w<<<cdiv(128 * 1024, T), T>>>(W1, W3T + W3T_OFF1, 128, 1024);
    k_split_w<<<cdiv(1024 * 512, T), T>>>(W2, W3T + W3T_OFF2, 1024, 512);
    k_split_w<<<cdiv(512 * 256, T), T>>>(W3, W3T + W3T_OFF3, 512, 256);
    k_split_w<<<cdiv(256 * 64, T), T>>>(W4, W3T + W3T_OFF4, 256, 64);

    // Layer 1: pre-aggregate x (width 128), split -> XA(256), GEMM+bias+relu -> XB(2048)
    k_selfinit<32><<<cdiv((long long)NN * 32, T), T>>>(x, dinv, A);
    k_scatter<32><<<cdiv((long long)NE * 32, T), T>>>(x, A, src, dst, norm);
    k_split_act<128><<<cdiv((long long)NN * 32, T), T>>>(A, XA);
    {
        dim3 g(1024 / 128, MB);
        gemm_mma<128, 0><<<g, 256, SMEM128>>>(XA, W3T + W3T_OFF1, NN, 128, 1024,
                                              b1, nullptr, nullptr, nullptr, XB);
    }

    // Layer 2: 1024 -> 512
    {
        dim3 g(512 / 128, MB);
        gemm_mma<128, 1><<<g, 256, SMEM128>>>(XB, W3T + W3T_OFF2, NN, 1024, 512,
                                              nullptr, A, C, dinv, nullptr);
    }
    k_scatter<128><<<cdiv((long long)NE * 128, T), T>>>(A, C, src, dst, norm);
    k_bias_relu_split<512><<<cdiv((long long)NN * 128, T), T>>>(C, b2, XA);

    // Layer 3: 512 -> 256
    {
        dim3 g(256 / 128, MB);
        gemm_mma<128, 1><<<g, 256, SMEM128>>>(XA, W3T + W3T_OFF3, NN, 512, 256,
                                              nullptr, A, C, dinv, nullptr);
    }
    k_scatter<64><<<cdiv((long long)NE * 64, T), T>>>(A, C, src, dst, norm);
    k_bias_relu_split<256><<<cdiv((long long)NN * 64, T), T>>>(C, b3, XB);

    // Layer 4: 256 -> 64
    {
        dim3 g(1, MB);
        gemm_mma<64, 1><<<g, 256, SMEM64>>>(XB, W3T + W3T_OFF4, NN, 256, 64,
                                            nullptr, A, C, dinv, nullptr);
    }
    k_scatter<16><<<cdiv((long long)NE * 16, T), T>>>(A, C, src, dst, norm);
    k_bias_relu<16><<<cdiv((long long)NN * 16, T), T>>>(C, b4, B64);

    // Layer 5: 64 -> 1
    k_gemv64<<<cdiv((long long)NN * 32, T), T>>>(B64, W5, A);
    k_selfinit1<<<cdiv(NN, T), T>>>(A, dinv, C);
    k_scatter1<<<cdiv(NE, T), T>>>(A, C, src, dst, norm);
    k_final<<<cdiv(NN, T), T>>>(C, b5, out);
}

// round 8
// speedup vs baseline: 2.4647x; 1.1984x over previous
#include <cuda_runtime.h>
#include <cuda_fp16.h>
#include <cstdint>

#define NN 50000
#define NE 400000

// ---------------- scratch (static device globals) ------------------------------
__device__ float g_A[(size_t)NN * 512];          // Hsc (dinv*h) GEMM outputs
__device__ float g_C[(size_t)NN * 512];          // gather accumulators
__device__ float g_B64[(size_t)NN * 64];         // layer-4 activations (fp32)
__device__ float g_Xsc[(size_t)NN * 128];        // dinv*x
__device__ __half g_XA[(size_t)NN * 1024];       // split activations (hi|lo)
__device__ __half g_XB[(size_t)NN * 2048];       // split activations (hi|lo)
__device__ __half g_W3T[2408448];                // split transposed weights (3K wide)
__device__ float g_dinv[NN];
__device__ int g_rowstart[NN + 1];
__device__ int g_cnt[NN];
__device__ int g_col[NE];

#define W3T_OFF1 0
#define W3T_OFF2 393216
#define W3T_OFF3 1966080
#define W3T_OFF4 2359296

// ---------------- PTX helpers ---------------------------------------------------
__device__ __forceinline__ uint32_t smem_u32(const void* p) {
    uint32_t a;
    asm("{ .reg .u64 t; cvta.to.shared.u64 t, %1; cvt.u32.u64 %0, t; }" : "=r"(a) : "l"(p));
    return a;
}
__device__ __forceinline__ void cp16(uint32_t dst, const void* src) {
    asm volatile("cp.async.cg.shared.global [%0], [%1], 16;" :: "r"(dst), "l"(src));
}
__device__ __forceinline__ void cp_commit() { asm volatile("cp.async.commit_group;"); }
__device__ __forceinline__ void cp_wait1() { asm volatile("cp.async.wait_group 1;"); }
__device__ __forceinline__ void cp_wait0() { asm volatile("cp.async.wait_group 0;"); }

__device__ __forceinline__ void ldsm_x4(uint32_t& r0, uint32_t& r1, uint32_t& r2,
                                        uint32_t& r3, uint32_t addr) {
    asm volatile("ldmatrix.sync.aligned.m8n8.x4.shared.b16 {%0,%1,%2,%3}, [%4];"
                 : "=r"(r0), "=r"(r1), "=r"(r2), "=r"(r3) : "r"(addr));
}
__device__ __forceinline__ void mma16816(float* c, const uint32_t* a, const uint32_t* b) {
    asm volatile("mma.sync.aligned.m16n8k16.row.col.f32.f16.f16.f32 "
                 "{%0,%1,%2,%3}, {%4,%5,%6,%7}, {%8,%9}, {%0,%1,%2,%3};"
                 : "+f"(c[0]), "+f"(c[1]), "+f"(c[2]), "+f"(c[3])
                 : "r"(a[0]), "r"(a[1]), "r"(a[2]), "r"(a[3]), "r"(b[0]), "r"(b[1]));
}

__device__ __forceinline__ void split_h(float v, __half& hi, __half& lo) {
    hi = __float2half_rn(v);
    lo = __float2half_rn(v - __half2float(hi));
}
__device__ __forceinline__ uint32_t pack2(__half a, __half b) {
    __half2 p = __halves2half2(a, b);
    return *reinterpret_cast<uint32_t*>(&p);
}

// ---------------- degree / dinv --------------------------------------------------
__global__ void k_fill1(float* p, int n) {
    int i = blockIdx.x * blockDim.x + threadIdx.x;
    if (i < n) p[i] = 1.0f;
}
__global__ void k_count(const int* __restrict__ dst, float* deg) {
    int e = blockIdx.x * blockDim.x + threadIdx.x;
    if (e < NE) atomicAdd(&deg[dst[e]], 1.0f);
}
__global__ void k_rsqrt_ip(float* p, int n) {
    int i = blockIdx.x * blockDim.x + threadIdx.x;
    if (i < n) p[i] = rsqrtf(p[i]);
}

// ---------------- CSR build -------------------------------------------------------
__global__ void k_zeroi(int* p, int n) {
    int i = blockIdx.x * blockDim.x + threadIdx.x;
    if (i < n) p[i] = 0;
}
__global__ void k_indeg(const int* __restrict__ dst, int* cnt) {
    int e = blockIdx.x * blockDim.x + threadIdx.x;
    if (e < NE) atomicAdd(&cnt[dst[e]], 1);
}
// single-block exclusive scan over NN counts -> rowstart[0..NN]
__global__ void k_scan(const int* __restrict__ cnt, int* __restrict__ rowstart) {
    __shared__ int sh[1024];
    const int t = threadIdx.x;
    const int CH = (NN + 1023) / 1024;
    const int base = t * CH;
    int s = 0;
    for (int i = 0; i < CH; i++) {
        int g = base + i;
        if (g < NN) s += cnt[g];
    }
    sh[t] = s;
    __syncthreads();
    for (int off = 1; off < 1024; off <<= 1) {
        int v = (t >= off) ? sh[t - off] : 0;
        __syncthreads();
        sh[t] += v;
        __syncthreads();
    }
    int run = sh[t] - s;  // exclusive base
    for (int i = 0; i < CH; i++) {
        int g = base + i;
        if (g < NN) { rowstart[g] = run; run += cnt[g]; }
    }
    if (t == 1023) rowstart[NN] = sh[1023];
}
__global__ void k_fillcsr(const int* __restrict__ src, const int* __restrict__ dst,
                          const int* __restrict__ rowstart, int* cnt, int* __restrict__ col) {
    int e = blockIdx.x * blockDim.x + threadIdx.x;
    if (e >= NE) return;
    int d = dst[e];
    int pos = rowstart[d] + atomicAdd(&cnt[d], 1);
    col[pos] = src[e];
}

// ---------------- gather aggregation (warp per node) ------------------------------
// agg[d,:] = Hsc[d,:] + sum_{s in in(d)} Hsc[s,:]       (F = 32*JF floats)
template<int JF>
__global__ void k_gather(const float* __restrict__ Hsc,
                         const int* __restrict__ rowstart, const int* __restrict__ col,
                         float* __restrict__ agg) {
    int gt = blockIdx.x * blockDim.x + threadIdx.x;
    int w = gt >> 5, lane = gt & 31;
    if (w >= NN) return;
    constexpr int F = 32 * JF;
    float acc[JF];
    const float* self = Hsc + (size_t)w * F;
#pragma unroll
    for (int j = 0; j < JF; j++) acc[j] = __ldg(self + j * 32 + lane);
    int e0 = rowstart[w], e1 = rowstart[w + 1];
    for (int e = e0; e < e1; e++) {
        const float* r = Hsc + (size_t)col[e] * F;
#pragma unroll
        for (int j = 0; j < JF; j++) acc[j] += __ldg(r + j * 32 + lane);
    }
    float* o = agg + (size_t)w * F;
#pragma unroll
    for (int j = 0; j < JF; j++) o[j * 32 + lane] = acc[j];
}

__global__ void k_gather1(const float* __restrict__ Hsc,
                          const int* __restrict__ rowstart, const int* __restrict__ col,
                          float* __restrict__ agg) {
    int i = blockIdx.x * blockDim.x + threadIdx.x;
    if (i >= NN) return;
    float acc = __ldg(Hsc + i);
    int e0 = rowstart[i], e1 = rowstart[i + 1];
    for (int e = e0; e < e1; e++) acc += __ldg(Hsc + col[e]);
    agg[i] = acc;
}

// ---------------- elementwise ------------------------------------------------------
// rows scaled by dinv (width F4 float4 units per row)
template<int F4>
__global__ void k_scale_rows(const float* __restrict__ in, const float* __restrict__ dinv,
                             float* __restrict__ out) {
    long long idx = (long long)blockIdx.x * blockDim.x + threadIdx.x;
    if (idx >= (long long)NN * F4) return;
    int i = (int)(idx / F4);
    float s = dinv[i];
    float4 v = ((const float4*)in)[idx];
    v.x *= s; v.y *= s; v.z *= s; v.w *= s;
    ((float4*)out)[idx] = v;
}

// X = split(dinv[m]*agg)  (no bias/relu; layer-1 pre-agg)
template<int K>
__global__ void k_scale_split(const float* __restrict__ in, const float* __restrict__ dinv,
                              __half* __restrict__ out) {
    long long idx = (long long)blockIdx.x * blockDim.x + threadIdx.x;
    if (idx >= (long long)NN * (K / 4)) return;
    int m = (int)(idx / (K / 4));
    int q = (int)(idx % (K / 4));
    int k = q * 4;
    float s = dinv[m];
    float4 v = ((const float4*)in)[idx];
    v.x *= s; v.y *= s; v.z *= s; v.w *= s;
    __half h[4], l[4];
    split_h(v.x, h[0], l[0]); split_h(v.y, h[1], l[1]);
    split_h(v.z, h[2], l[2]); split_h(v.w, h[3], l[3]);
    __half* row = out + (size_t)m * (2 * K);
    *(uint2*)(row + k)     = make_uint2(pack2(h[0], h[1]), pack2(h[2], h[3]));
    *(uint2*)(row + K + k) = make_uint2(pack2(l[0], l[1]), pack2(l[2], l[3]));
}

// X = split(relu(dinv[m]*agg + b))
template<int K>
__global__ void k_postagg_split(const float* __restrict__ in, const float* __restrict__ b,
                                const float* __restrict__ dinv, __half* __restrict__ out) {
    long long idx = (long long)blockIdx.x * blockDim.x + threadIdx.x;
    if (idx >= (long long)NN * (K / 4)) return;
    int m = (int)(idx / (K / 4));
    int q = (int)(idx % (K / 4));
    int k = q * 4;
    float s = dinv[m];
    float4 v = ((const float4*)in)[idx];
    float4 bb = ((const float4*)b)[q];
    v.x = fmaxf(fmaf(s, v.x, bb.x), 0.f);
    v.y = fmaxf(fmaf(s, v.y, bb.y), 0.f);
    v.z = fmaxf(fmaf(s, v.z, bb.z), 0.f);
    v.w = fmaxf(fmaf(s, v.w, bb.w), 0.f);
    __half h[4], l[4];
    split_h(v.x, h[0], l[0]); split_h(v.y, h[1], l[1]);
    split_h(v.z, h[2], l[2]); split_h(v.w, h[3], l[3]);
    __half* row = out + (size_t)m * (2 * K);
    *(uint2*)(row + k)     = make_uint2(pack2(h[0], h[1]), pack2(h[2], h[3]));
    *(uint2*)(row + K + k) = make_uint2(pack2(l[0], l[1]), pack2(l[2], l[3]));
}

// fp32 out = relu(dinv[m]*agg + b)   (layer-4 post)
template<int F4>
__global__ void k_postagg(const float* __restrict__ in, const float* __restrict__ b,
                          const float* __restrict__ dinv, float* __restrict__ out) {
    long long idx = (long long)blockIdx.x * blockDim.x + threadIdx.x;
    if (idx >= (long long)NN * F4) return;
    int m = (int)(idx / F4);
    int f = (int)(idx % F4);
    float s = dinv[m];
    float4 bb = ((const float4*)b)[f];
    float4 v = ((const float4*)in)[idx];
    v.x = fmaxf(fmaf(s, v.x, bb.x), 0.f);
    v.y = fmaxf(fmaf(s, v.y, bb.y), 0.f);
    v.z = fmaxf(fmaf(s, v.z, bb.z), 0.f);
    v.w = fmaxf(fmaf(s, v.w, bb.w), 0.f);
    ((float4*)out)[idx] = v;
}

// W3T row n (width 3K): [Whi | Wlo | Whi], from W[k][n]
__global__ void k_split_w(const float* __restrict__ W, __half* __restrict__ out,
                          int K, int N) {
    long long idx = (long long)blockIdx.x * blockDim.x + threadIdx.x;
    if (idx >= (long long)K * N) return;
    int n = (int)(idx / K);
    int k = (int)(idx % K);
    float v = W[(size_t)k * N + n];
    __half h, l;
    split_h(v, h, l);
    __half* row = out + (size_t)n * (3 * K);
    row[k] = h;
    row[K + k] = l;
    row[2 * K + k] = h;
}

// ---------------- warp-MMA fp16 GEMM ---------------------------------------------
// C[M,N] = Asplit[M,2K] (logical [hi|hi|lo], 3K) @ W3T[N,3K]^T, fp32 accumulate.
// EPI 0: out = relu(C + bias) -> split fp16 to Xout (row width 2N)
// EPI 1: Hout = dinv[m] * C
template<int BN, int EPI>
__global__ void __launch_bounds__(256, 2)
gemm_mma(const __half* __restrict__ A2, const __half* __restrict__ W3T,
         int M, int K, int N,
         const float* __restrict__ bias,
         float* __restrict__ Hout,
         const float* __restrict__ dinv,
         __half* __restrict__ Xout) {
    extern __shared__ char smem[];
    constexpr int WN = BN / 2;
    constexpr int NT = WN / 8;
    constexpr int A_SZ = 128 * 128;
    constexpr int B_SZ = BN * 128;

    const int tid = threadIdx.x;
    const int m0 = blockIdx.y * 128;
    const int n0 = blockIdx.x * BN;
    const int Kphys = 2 * K;
    const int K3 = 3 * K;
    const int NCH = K3 >> 6;

    const uint32_t sA = smem_u32(smem);
    const uint32_t sB = sA + A_SZ;
    const uint32_t stageStride = A_SZ + B_SZ;

    const int lr = tid >> 3;
    const int lc = tid & 7;

    auto issue = [&](int ci) {
        const int s = ci & 1;
        const int kpos = ci * 64;
        const int aoff = (kpos >= K) ? kpos - K : kpos;
        const uint32_t dA = sA + s * stageStride;
        const uint32_t dB = sB + s * stageStride;
#pragma unroll
        for (int t = 0; t < 4; t++) {
            int r = lr + t * 32;
            int gm = m0 + r; if (gm >= M) gm = M - 1;
            const void* src = (const char*)A2 + ((size_t)gm * Kphys + aoff + lc * 8) * 2;
            cp16(dA + r * 128 + ((lc ^ (r & 7)) << 4), src);
        }
#pragma unroll
        for (int t = 0; t < BN / 32; t++) {
            int r = lr + t * 32;
            const void* src = (const char*)W3T + ((size_t)(n0 + r) * K3 + kpos + lc * 8) * 2;
            cp16(dB + r * 128 + ((lc ^ (r & 7)) << 4), src);
        }
        cp_commit();
    };

    const int w = tid >> 5, lane = tid & 31;
    const int wm = w & 3, wn = w >> 2;

    float acc[2][NT][4];
#pragma unroll
    for (int mt = 0; mt < 2; mt++)
#pragma unroll
        for (int nt = 0; nt < NT; nt++)
#pragma unroll
            for (int j = 0; j < 4; j++) acc[mt][nt][j] = 0.f;

    issue(0);
    for (int ci = 0; ci < NCH; ci++) {
        if (ci + 1 < NCH) { issue(ci + 1); cp_wait1(); }
        else              { cp_wait0(); }
        __syncthreads();
        const int s = ci & 1;
        const uint32_t stA = sA + s * stageStride;
        const uint32_t stB = sB + s * stageStride;
#pragma unroll
        for (int kk = 0; kk < 4; kk++) {
            uint32_t af[2][4];
#pragma unroll
            for (int mt = 0; mt < 2; mt++) {
                int row = wm * 32 + mt * 16 + (lane & 15);
                int c = kk * 2 + (lane >> 4);
                ldsm_x4(af[mt][0], af[mt][1], af[mt][2], af[mt][3],
                        stA + row * 128 + ((c ^ (row & 7)) << 4));
            }
            uint32_t bf[NT][2];
#pragma unroll
            for (int bt = 0; bt < NT / 2; bt++) {
                int j = lane >> 3;
                int row = wn * WN + bt * 16 + ((j >> 1) << 3) + (lane & 7);
                int c = kk * 2 + (j & 1);
                ldsm_x4(bf[2 * bt][0], bf[2 * bt][1], bf[2 * bt + 1][0], bf[2 * bt + 1][1],
                        stB + row * 128 + ((c ^ (row & 7)) << 4));
            }
#pragma unroll
            for (int mt = 0; mt < 2; mt++)
#pragma unroll
                for (int nt = 0; nt < NT; nt++)
                    mma16816(acc[mt][nt], af[mt], bf[nt]);
        }
        __syncthreads();
    }

    // ---------------- epilogue ----------------
#pragma unroll
    for (int mt = 0; mt < 2; mt++) {
#pragma unroll
        for (int rh = 0; rh < 2; rh++) {
            int row = wm * 32 + mt * 16 + rh * 8 + (lane >> 2);
            int gm = m0 + row;
            if (gm >= M) continue;
            if constexpr (EPI == 1) {
                float s = dinv[gm];
#pragma unroll
                for (int nt = 0; nt < NT; nt++) {
                    int col = n0 + wn * WN + nt * 8 + (lane & 3) * 2;
                    float c0 = acc[mt][nt][rh * 2], c1 = acc[mt][nt][rh * 2 + 1];
                    *(float2*)(Hout + (size_t)gm * N + col) = make_float2(s * c0, s * c1);
                }
            } else {
#pragma unroll
                for (int nt = 0; nt < NT; nt++) {
                    int col = n0 + wn * WN + nt * 8 + (lane & 3) * 2;
                    float v0 = fmaxf(acc[mt][nt][rh * 2]     + __ldg(bias + col),     0.f);
                    float v1 = fmaxf(acc[mt][nt][rh * 2 + 1] + __ldg(bias + col + 1), 0.f);
                    __half h0, l0, h1, l1;
                    split_h(v0, h0, l0);
                    split_h(v1, h1, l1);
                    size_t base = (size_t)gm * (size_t)(2 * N) + col;
                    *(uint32_t*)(Xout + base)     = pack2(h0, h1);
                    *(uint32_t*)(Xout + base + N) = pack2(l0, l1);
                }
            }
        }
    }
}

// ---------------- last layer (K=64 -> F=1) ----------------------------------------
__global__ void k_gemv64(const float* __restrict__ X, const float* __restrict__ w,
                         const float* __restrict__ dinv, float* __restrict__ out) {
    int gt = blockIdx.x * blockDim.x + threadIdx.x;
    int row = gt >> 5;
    int lane = gt & 31;
    if (row >= NN) return;
    float s = X[(long long)row * 64 + lane] * w[lane]
            + X[(long long)row * 64 + 32 + lane] * w[32 + lane];
#pragma unroll
    for (int o = 16; o; o >>= 1) s += __shfl_down_sync(0xffffffffu, s, o);
    if (lane == 0) out[row] = dinv[row] * s;
}

__global__ void k_final(const float* __restrict__ in, const float* __restrict__ b,
                        const float* __restrict__ dinv, float* __restrict__ out) {
    int i = blockIdx.x * blockDim.x + threadIdx.x;
    if (i >= NN) return;
    out[i] = fmaxf(fmaf(dinv[i], in[i], b[0]), 0.f);
}

// ---------------- driver ----------------------------------------------------------
static inline int cdiv(long long a, long long b) { return (int)((a + b - 1) / b); }

extern "C" void kernel_launch(void* const* d_in, const int* in_sizes, int n_in,
                              void* d_out, int out_size) {
    const float* x   = (const float*)d_in[0];
    const int*   src = (const int*)d_in[1];
    const int*   dst = src + NE;
    const float* W1 = (const float*)d_in[2];  const float* b1 = (const float*)d_in[3];
    const float* W2 = (const float*)d_in[4];  const float* b2 = (const float*)d_in[5];
    const float* W3 = (const float*)d_in[6];  const float* b3 = (const float*)d_in[7];
    const float* W4 = (const float*)d_in[8];  const float* b4 = (const float*)d_in[9];
    const float* W5 = (const float*)d_in[10]; const float* b5 = (const float*)d_in[11];
    float* out = (float*)d_out;

    float *A, *C, *B64, *Xsc, *dinv;
    __half *XA, *XB, *W3T;
    int *rowstart, *cnt, *col;
    cudaGetSymbolAddress((void**)&A, g_A);
    cudaGetSymbolAddress((void**)&C, g_C);
    cudaGetSymbolAddress((void**)&B64, g_B64);
    cudaGetSymbolAddress((void**)&Xsc, g_Xsc);
    cudaGetSymbolAddress((void**)&XA, g_XA);
    cudaGetSymbolAddress((void**)&XB, g_XB);
    cudaGetSymbolAddress((void**)&W3T, g_W3T);
    cudaGetSymbolAddress((void**)&dinv, g_dinv);
    cudaGetSymbolAddress((void**)&rowstart, g_rowstart);
    cudaGetSymbolAddress((void**)&cnt, g_cnt);
    cudaGetSymbolAddress((void**)&col, g_col);

    const int SMEM128 = 2 * (128 * 128 + 128 * 128);  // 65536
    const int SMEM64  = 2 * (128 * 128 + 64 * 128);   // 49152
    cudaFuncSetAttribute(gemm_mma<128, 0>, cudaFuncAttributeMaxDynamicSharedMemorySize, SMEM128);
    cudaFuncSetAttribute(gemm_mma<128, 1>, cudaFuncAttributeMaxDynamicSharedMemorySize, SMEM128);
    cudaFuncSetAttribute(gemm_mma<64, 1>,  cudaFuncAttributeMaxDynamicSharedMemorySize, SMEM64);

    const int T = 256;
    const int MB = cdiv(NN, 128);        // 391
    const int GW = cdiv((long long)NN * 32, T);  // gather: warp per node

    // degree / dinv (deg includes self-loop: start at 1)
    k_fill1<<<cdiv(NN, T), T>>>(dinv, NN);
    k_count<<<cdiv(NE, T), T>>>(dst, dinv);
    k_rsqrt_ip<<<cdiv(NN, T), T>>>(dinv, NN);

    // CSR build (incoming edges per dst, storing src)
    k_zeroi<<<cdiv(NN, T), T>>>(cnt, NN);
    k_indeg<<<cdiv(NE, T), T>>>(dst, cnt);
    k_scan<<<1, 1024>>>(cnt, rowstart);
    k_zeroi<<<cdiv(NN, T), T>>>(cnt, NN);
    k_fillcsr<<<cdiv(NE, T), T>>>(src, dst, rowstart, cnt, col);

    // weight splits
    k_split_w<<<cdiv(128 * 1024, T), T>>>(W1, W3T + W3T_OFF1, 128, 1024);
    k_split_w<<<cdiv(1024 * 512, T), T>>>(W2, W3T + W3T_OFF2, 1024, 512);
    k_split_w<<<cdiv(512 * 256, T), T>>>(W3, W3T + W3T_OFF3, 512, 256);
    k_split_w<<<cdiv(256 * 64, T), T>>>(W4, W3T + W3T_OFF4, 256, 64);

    // Layer 1: Xsc = dinv*x ; gather(128) ; split(dinv*agg) ; GEMM+bias+relu -> XB
    k_scale_rows<32><<<cdiv((long long)NN * 32, T), T>>>(x, dinv, Xsc);
    k_gather<4><<<GW, T>>>(Xsc, rowstart, col, C);
    k_scale_split<128><<<cdiv((long long)NN * 32, T), T>>>(C, dinv, XA);
    {
        dim3 g(1024 / 128, MB);
        gemm_mma<128, 0><<<g, 256, SMEM128>>>(XA, W3T + W3T_OFF1, NN, 128, 1024,
                                              b1, nullptr, nullptr, XB);
    }

    // Layer 2: 1024 -> 512
    {
        dim3 g(512 / 128, MB);
        gemm_mma<128, 1><<<g, 256, SMEM128>>>(XB, W3T + W3T_OFF2, NN, 1024, 512,
                                              nullptr, A, dinv, nullptr);
    }
    k_gather<16><<<GW, T>>>(A, rowstart, col, C);
    k_postagg_split<512><<<cdiv((long long)NN * 128, T), T>>>(C, b2, dinv, XA);

    // Layer 3: 512 -> 256
    {
        dim3 g(256 / 128, MB);
        gemm_mma<128, 1><<<g, 256, SMEM128>>>(XA, W3T + W3T_OFF3, NN, 512, 256,
                                              nullptr, A, dinv, nullptr);
    }
    k_gather<8><<<GW, T>>>(A, rowstart, col, C);
    k_postagg_split<256><<<cdiv((long long)NN * 64, T), T>>>(C, b3, dinv, XB);

    // Layer 4: 256 -> 64
    {
        dim3 g(1, MB);
        gemm_mma<64, 1><<<g, 256, SMEM64>>>(XB, W3T + W3T_OFF4, NN, 256, 64,
                                            nullptr, A, dinv, nullptr);
    }
    k_gather<2><<<GW, T>>>(A, rowstart, col, C);
    k_postagg<16><<<cdiv((long long)NN * 16, T), T>>>(C, b4, dinv, B64);

    // Layer 5: 64 -> 1
    k_gemv64<<<cdiv((long long)NN * 32, T), T>>>(B64, W5, dinv, A);
    k_gather1<<<cdiv(NN, T), T>>>(A, rowstart, col, C);
    k_final<<<cdiv(NN, T), T>>>(C, b5, dinv, out);
}